// round 1
// baseline (speedup 1.0000x reference)
#include <cuda_runtime.h>
#include <math.h>

#define HID 512
#define HID4 (HID / 4)
#define MAXN 262144
#define MAXB 4096

// -------- device scratch (no allocations allowed) --------
__device__ float d_scr[MAXN];        // logits -> exp -> s -> e  (in place)
__device__ int   d_b32[MAXN];        // batch ids as int32
__device__ int   d_segstart[MAXB];
__device__ float d_segmax[MAXB];
__device__ float d_segden[MAXB];
__device__ float d_gmax;
__device__ float d_gsum;

__device__ __forceinline__ void atomicMaxF(float* addr, float v) {
    if (v >= 0.0f) atomicMax((int*)addr, __float_as_int(v));
    else           atomicMin((unsigned int*)addr, __float_as_uint(v));
}

// K0: dtype-detect + convert batch, mark segment starts, init scratch.
// batch is sorted, every id in [0,B) appears, last value == B-1.
// If the buffer is int64 (little-endian), int32 index n-1 lands mid-buffer
// (~median id != B-1), so the check is unambiguous.
__global__ void k0_init(const int* __restrict__ batch_raw, int n, int nb) {
    int i = blockIdx.x * blockDim.x + threadIdx.x;
    bool is32 = (batch_raw[n - 1] == nb - 1);
    if (i < n) {
        int b  = is32 ? batch_raw[i]       : batch_raw[2 * i];
        d_b32[i] = b;
        int bp = (i == 0) ? -1 : (is32 ? batch_raw[i - 1] : batch_raw[2 * (i - 1)]);
        if (b != bp) d_segstart[b] = i;
    }
    if (i < nb) { d_segmax[i] = 0.0f; d_segden[i] = 0.0f; }
    if (i == 0) { d_gmax = -INFINITY; d_gsum = 0.0f; }
}

// K1: logits[row] = dot(x[row], W) + b ; warp per row, float4, W in smem.
// Also block-reduced global max -> one atomic per block.
__global__ void __launch_bounds__(256) k1_logits(
    const float4* __restrict__ x, const float4* __restrict__ W,
    const float* __restrict__ bias, int n)
{
    __shared__ float4 sW[HID4];
    __shared__ float  smax[8];
    int tid = threadIdx.x;
    for (int i = tid; i < HID4; i += 256) sW[i] = W[i];
    __syncthreads();

    int warp = tid >> 5, lane = tid & 31;
    int row  = blockIdx.x * 8 + warp;
    float dot = 0.0f;
    if (row < n) {
        const float4* xr = x + (size_t)row * HID4;
#pragma unroll
        for (int c = 0; c < 4; ++c) {
            float4 v = xr[lane + c * 32];
            float4 w = sW[lane + c * 32];
            dot += v.x * w.x + v.y * w.y + v.z * w.z + v.w * w.w;
        }
    }
#pragma unroll
    for (int o = 16; o; o >>= 1) dot += __shfl_xor_sync(0xFFFFFFFFu, dot, o);
    float logit = dot + bias[0];
    if (row < n && lane == 0) d_scr[row] = logit;

    if (lane == 0) smax[warp] = (row < n) ? logit : -INFINITY;
    __syncthreads();
    if (tid == 0) {
        float bm = smax[0];
#pragma unroll
        for (int w = 1; w < 8; ++w) bm = fmaxf(bm, smax[w]);
        atomicMaxF(&d_gmax, bm);
    }
}

// K2: e = exp(logit - gmax) in place; block-reduced sum -> one atomic per block.
__global__ void __launch_bounds__(256) k2_exp(int n) {
    __shared__ float ssum[8];
    int i = blockIdx.x * blockDim.x + threadIdx.x;
    float gmax = d_gmax;
    float e = 0.0f;
    if (i < n) { e = expf(d_scr[i] - gmax); d_scr[i] = e; }
    float s = e;
#pragma unroll
    for (int o = 16; o; o >>= 1) s += __shfl_xor_sync(0xFFFFFFFFu, s, o);
    int warp = threadIdx.x >> 5, lane = threadIdx.x & 31;
    if (lane == 0) ssum[warp] = s;
    __syncthreads();
    if (threadIdx.x == 0) {
        float bs = 0.0f;
#pragma unroll
        for (int w = 0; w < 8; ++w) bs += ssum[w];
        atomicAdd(&d_gsum, bs);
    }
}

// K3: s = e / gsum in place; per-segment max (s > 0 -> int-bit atomicMax valid).
__global__ void k3_s(int n) {
    int i = blockIdx.x * blockDim.x + threadIdx.x;
    if (i >= n) return;
    float s = d_scr[i] / d_gsum;
    d_scr[i] = s;
    atomicMax((int*)&d_segmax[d_b32[i]], __float_as_int(s));
}

// K4: e = exp(s - segmax[b]) in place; per-segment denom sum.
__global__ void k4_e(int n) {
    int i = blockIdx.x * blockDim.x + threadIdx.x;
    if (i >= n) return;
    int b = d_b32[i];
    float e = expf(d_scr[i] - d_segmax[b]);
    d_scr[i] = e;
    atomicAdd(&d_segden[b], e);
}

// K5: one block per segment; contiguous rows, zero atomics.
// 128 threads, each owns one float4 column; 4-row unroll for MLP.
__global__ void __launch_bounds__(128) k5_out(
    const float4* __restrict__ x, float4* __restrict__ out, int n, int nb)
{
    int b = blockIdx.x;
    int start = d_segstart[b];
    int end   = (b == nb - 1) ? n : d_segstart[b + 1];
    float inv = 1.0f / d_segden[b];
    int c = threadIdx.x;  // float4 column 0..127

    float4 acc = make_float4(0.f, 0.f, 0.f, 0.f);
    int r = start;
    for (; r + 4 <= end; r += 4) {
        float a0 = d_scr[r], a1 = d_scr[r + 1], a2 = d_scr[r + 2], a3 = d_scr[r + 3];
        float4 v0 = x[(size_t)(r    ) * HID4 + c];
        float4 v1 = x[(size_t)(r + 1) * HID4 + c];
        float4 v2 = x[(size_t)(r + 2) * HID4 + c];
        float4 v3 = x[(size_t)(r + 3) * HID4 + c];
        acc.x += v0.x * a0 + v1.x * a1 + v2.x * a2 + v3.x * a3;
        acc.y += v0.y * a0 + v1.y * a1 + v2.y * a2 + v3.y * a3;
        acc.z += v0.z * a0 + v1.z * a1 + v2.z * a2 + v3.z * a3;
        acc.w += v0.w * a0 + v1.w * a1 + v2.w * a2 + v3.w * a3;
    }
    for (; r < end; ++r) {
        float a = d_scr[r];
        float4 v = x[(size_t)r * HID4 + c];
        acc.x += v.x * a; acc.y += v.y * a; acc.z += v.z * a; acc.w += v.w * a;
    }
    acc.x *= inv; acc.y *= inv; acc.z *= inv; acc.w *= inv;
    out[(size_t)b * HID4 + c] = acc;
}

extern "C" void kernel_launch(void* const* d_in, const int* in_sizes, int n_in,
                              void* d_out, int out_size) {
    const float* x     = (const float*)d_in[0];
    const int*   batch = (const int*)d_in[1];
    const float* W     = (const float*)d_in[2];
    const float* bias  = (const float*)d_in[3];
    float*       out   = (float*)d_out;

    int n  = in_sizes[0] / HID;   // 262144
    int nb = out_size   / HID;    // 4096

    const int T = 256;
    int gN = (n + T - 1) / T;

    k0_init <<<gN, T>>>(batch, n, nb);
    k1_logits<<<(n + 7) / 8, 256>>>((const float4*)x, (const float4*)W, bias, n);
    k2_exp  <<<gN, T>>>(n);
    k3_s    <<<gN, T>>>(n);
    k4_e    <<<gN, T>>>(n);
    k5_out  <<<nb, 128>>>((const float4*)x, (float4*)out, n, nb);
}

// round 2
// speedup vs baseline: 1.1274x; 1.1274x over previous
#include <cuda_runtime.h>
#include <math.h>

#define HID 512
#define HID4 (HID / 4)
#define MAXN 262144
#define MAXB 4096
#define NPART 64
#define SMEM_CAP 1024   // max segment length for smem fast path (expected max ~110)

// -------- device scratch (no allocations allowed) --------
__device__ float d_e[MAXN];          // e_i = exp(logit_i)
__device__ int   d_segstart[MAXB];
__device__ float d_part[NPART];      // gsum partials
__device__ float d_gsum;

// K_init: zero gsum partials.
__global__ void k_init() {
    if (threadIdx.x < NPART) d_part[threadIdx.x] = 0.0f;
}

// K1: e[row] = exp(dot(x[row], W) + b); block-reduced gsum into partial bins;
// segment-start detection (batch sorted, every id present). 256 thr, 32 rows/block.
__global__ void __launch_bounds__(256) k1_logits(
    const float4* __restrict__ x, const float4* __restrict__ W,
    const float* __restrict__ bias, const int* __restrict__ batch_raw,
    int n, int nb)
{
    __shared__ float4 sW[HID4];
    __shared__ float  ssum[8];
    int tid = threadIdx.x;
    for (int i = tid; i < HID4; i += 256) sW[i] = W[i];
    __syncthreads();

    // dtype detect: int32 iff last int32 word equals nb-1 (sorted, ends at nb-1)
    bool is32 = (batch_raw[n - 1] == nb - 1);
    float b0 = bias[0];

    int warp = tid >> 5, lane = tid & 31;
    int row0 = blockIdx.x * 32 + warp * 4;

    float wsum = 0.0f;
#pragma unroll
    for (int k = 0; k < 4; ++k) {
        int row = row0 + k;
        float dot = 0.0f;
        if (row < n) {
            const float4* xr = x + (size_t)row * HID4;
#pragma unroll
            for (int c = 0; c < 4; ++c) {
                float4 v = xr[lane + c * 32];
                float4 w = sW[lane + c * 32];
                dot += v.x * w.x + v.y * w.y + v.z * w.z + v.w * w.w;
            }
        }
#pragma unroll
        for (int o = 16; o; o >>= 1) dot += __shfl_xor_sync(0xFFFFFFFFu, dot, o);
        if (row < n) {
            float e = expf(dot + b0);
            if (lane == 0) {
                d_e[row] = e;
                wsum += e;
                int b  = is32 ? batch_raw[row] : batch_raw[2 * row];
                int bp = (row == 0) ? -1 : (is32 ? batch_raw[row - 1] : batch_raw[2 * (row - 1)]);
                if (b != bp) d_segstart[b] = row;
            }
        }
    }
    if (lane == 0) ssum[warp] = wsum;
    __syncthreads();
    if (tid == 0) {
        float bs = 0.0f;
#pragma unroll
        for (int w = 0; w < 8; ++w) bs += ssum[w];
        atomicAdd(&d_part[blockIdx.x & (NPART - 1)], bs);
    }
}

// K_reduce: 1 warp sums the 64 partials.
__global__ void k_reduce() {
    int t = threadIdx.x;
    float v = d_part[t] + d_part[t + 32];
#pragma unroll
    for (int o = 16; o; o >>= 1) v += __shfl_xor_sync(0xFFFFFFFFu, v, o);
    if (t == 0) d_gsum = v;
}

// K5: one block per segment. Block-local segment softmax (on s = e/gsum via
// exp((e - emax)/gsum)) + weighted column sum. Zero atomics.
__global__ void __launch_bounds__(128) k5_out(
    const float4* __restrict__ x, float4* __restrict__ out, int n, int nb)
{
    __shared__ float s_a[SMEM_CAP];
    __shared__ float s_red[4];
    __shared__ float s_bc[2];   // [0]=emax, [1]=inv_den

    int b = blockIdx.x;
    int start = d_segstart[b];
    int end   = (b == nb - 1) ? n : d_segstart[b + 1];
    int L     = end - start;
    int t = threadIdx.x, warp = t >> 5, lane = t & 31;
    float rg = 1.0f / d_gsum;

    // ---- phase 1a: segment max of e ----
    float m = -INFINITY;
    for (int r = start + t; r < end; r += 128) m = fmaxf(m, d_e[r]);
#pragma unroll
    for (int o = 16; o; o >>= 1) m = fmaxf(m, __shfl_xor_sync(0xFFFFFFFFu, m, o));
    if (lane == 0) s_red[warp] = m;
    __syncthreads();
    if (t == 0) {
        float bm = fmaxf(fmaxf(s_red[0], s_red[1]), fmaxf(s_red[2], s_red[3]));
        s_bc[0] = bm;
    }
    __syncthreads();
    float emax = s_bc[0];

    // ---- phase 1b: e' = exp((e - emax)/gsum), denom ----
    bool fast = (L <= SMEM_CAP);
    float sum = 0.0f;
    for (int r = start + t; r < end; r += 128) {
        float v = expf((d_e[r] - emax) * rg);
        if (fast) s_a[r - start] = v;
        sum += v;
    }
#pragma unroll
    for (int o = 16; o; o >>= 1) sum += __shfl_xor_sync(0xFFFFFFFFu, sum, o);
    if (lane == 0) s_red[warp] = sum;
    __syncthreads();
    if (t == 0) s_bc[1] = 1.0f / (s_red[0] + s_red[1] + s_red[2] + s_red[3]);
    __syncthreads();
    float inv = s_bc[1];

    // ---- phase 2: weighted column sum; thread t owns float4 column t ----
    float4 acc = make_float4(0.f, 0.f, 0.f, 0.f);
    if (fast) {
        int r = start;
        for (; r + 4 <= end; r += 4) {
            int j = r - start;
            float a0 = s_a[j], a1 = s_a[j + 1], a2 = s_a[j + 2], a3 = s_a[j + 3];
            float4 v0 = x[(size_t)(r    ) * HID4 + t];
            float4 v1 = x[(size_t)(r + 1) * HID4 + t];
            float4 v2 = x[(size_t)(r + 2) * HID4 + t];
            float4 v3 = x[(size_t)(r + 3) * HID4 + t];
            acc.x += v0.x * a0 + v1.x * a1 + v2.x * a2 + v3.x * a3;
            acc.y += v0.y * a0 + v1.y * a1 + v2.y * a2 + v3.y * a3;
            acc.z += v0.z * a0 + v1.z * a1 + v2.z * a2 + v3.z * a3;
            acc.w += v0.w * a0 + v1.w * a1 + v2.w * a2 + v3.w * a3;
        }
        for (; r < end; ++r) {
            float a = s_a[r - start];
            float4 v = x[(size_t)r * HID4 + t];
            acc.x += v.x * a; acc.y += v.y * a; acc.z += v.z * a; acc.w += v.w * a;
        }
    } else {
        // fallback (virtually never taken): recompute e' on the fly
        for (int r = start; r < end; ++r) {
            float a = expf((d_e[r] - emax) * rg);
            float4 v = x[(size_t)r * HID4 + t];
            acc.x += v.x * a; acc.y += v.y * a; acc.z += v.z * a; acc.w += v.w * a;
        }
    }
    acc.x *= inv; acc.y *= inv; acc.z *= inv; acc.w *= inv;
    out[(size_t)b * HID4 + t] = acc;
}

extern "C" void kernel_launch(void* const* d_in, const int* in_sizes, int n_in,
                              void* d_out, int out_size) {
    const float* x     = (const float*)d_in[0];
    const int*   batch = (const int*)d_in[1];
    const float* W     = (const float*)d_in[2];
    const float* bias  = (const float*)d_in[3];
    float*       out   = (float*)d_out;

    int n  = in_sizes[0] / HID;   // 262144
    int nb = out_size   / HID;    // 4096

    k_init   <<<1, NPART>>>();
    k1_logits<<<(n + 31) / 32, 256>>>((const float4*)x, (const float4*)W, bias,
                                      batch, n, nb);
    k_reduce <<<1, 32>>>();
    k5_out   <<<nb, 128>>>((const float4*)x, (float4*)out, n, nb);
}